// round 8
// baseline (speedup 1.0000x reference)
#include <cuda_runtime.h>
#include <math.h>
#include <stdint.h>

#define LN2SQ 0.4804530139182014
#define LOG2E 1.4426950408889634f
#define PI_F  3.14159265359f
#define TWOPI3 2.0943951023931953f

typedef unsigned long long u64;

__device__ double g_accum = 0.0;
__device__ unsigned int g_count = 0u;

// ---- scalar MUFU intrinsics ----
__device__ __forceinline__ float f_rcp(float x)   { float y; asm("rcp.approx.f32 %0, %1;"   : "=f"(y) : "f"(x)); return y; }
__device__ __forceinline__ float f_rsqrt(float x) { float y; asm("rsqrt.approx.f32 %0, %1;" : "=f"(y) : "f"(x)); return y; }
__device__ __forceinline__ float f_sqrt(float x)  { float y; asm("sqrt.approx.f32 %0, %1;"  : "=f"(y) : "f"(x)); return y; }
__device__ __forceinline__ float f_lg2(float x)   { float y; asm("lg2.approx.f32 %0, %1;"   : "=f"(y) : "f"(x)); return y; }
__device__ __forceinline__ float f_cos(float x)   { float y; asm("cos.approx.f32 %0, %1;"   : "=f"(y) : "f"(x)); return y; }

// ---- packed f32x2 ops (sm_100+) ----
__device__ __forceinline__ u64 pk(float lo, float hi) { u64 r; asm("mov.b64 %0, {%1, %2};" : "=l"(r) : "f"(lo), "f"(hi)); return r; }
__device__ __forceinline__ void upk(u64 v, float& lo, float& hi) { asm("mov.b64 {%0, %1}, %2;" : "=f"(lo), "=f"(hi) : "l"(v)); }
__device__ __forceinline__ u64 add2(u64 a, u64 b) { u64 d; asm("add.rn.f32x2 %0, %1, %2;" : "=l"(d) : "l"(a), "l"(b)); return d; }
__device__ __forceinline__ u64 mul2(u64 a, u64 b) { u64 d; asm("mul.rn.f32x2 %0, %1, %2;" : "=l"(d) : "l"(a), "l"(b)); return d; }
__device__ __forceinline__ u64 fma2(u64 a, u64 b, u64 c) { u64 d; asm("fma.rn.f32x2 %0, %1, %2, %3;" : "=l"(d) : "l"(a), "l"(b), "l"(c)); return d; }
__device__ __forceinline__ u64 bc2(float c) { return pk(c, c); }
__device__ __forceinline__ u64 sub2(u64 a, u64 b, u64 neg1) { return fma2(b, neg1, a); }  // a - b

// scalar divided differences with the R5-proven degenerate guards (lg2 units)
__device__ __forceinline__ void divdiff(float w0, float w1, float w2,
                                        float& alp, float& bet, float& gam) {
    float f0 = f_lg2(w0);
    float f1 = f_lg2(w1);
    float f2 = f_lg2(w2);
    float e01 = w0 - w1, e12 = w1 - w2, e02 = w0 - w2;
    float d01 = (e01 > 0.01f * (w0 + w1)) ? (f0 - f1) * f_rcp(e01)
                                          : 2.0f * LOG2E * f_rcp(w0 + w1);
    float d12 = (e12 > 0.01f * (w1 + w2)) ? (f1 - f2) * f_rcp(e12)
                                          : 2.0f * LOG2E * f_rcp(w1 + w2);
    if (e02 > 0.005f * (w0 + w2)) {
        gam = (d01 - d12) * f_rcp(e02);
    } else {
        float q = (w0 + w1 + w2) * (1.0f / 3.0f);
        float iq = f_rcp(q);
        gam = -0.5f * LOG2E * iq * iq;
    }
    bet = d01 - gam * (w0 + w1);
    alp = f0 - d01 * w0 + gam * w0 * w1;
}

// Two matrix pairs (streams A and B), statement-interleaved so BOTH packed
// dependency chains stay live: ptxas cannot serialize them (the R7 failure).
__device__ __forceinline__ void pair2(const float* __restrict__ g1a, const float* __restrict__ g2a,
                                      const float* __restrict__ g1b, const float* __restrict__ g2b,
                                      float& outA, float& outB) {
    const u64 NEG1 = bc2(-1.0f);

    u64 a00A = pk(fabsf(g1a[0]), fabsf(g2a[0]));  u64 a00B = pk(fabsf(g1b[0]), fabsf(g2b[0]));
    u64 a10A = pk(fabsf(g1a[3]), fabsf(g2a[3]));  u64 a10B = pk(fabsf(g1b[3]), fabsf(g2b[3]));
    u64 a11A = pk(fabsf(g1a[4]), fabsf(g2a[4]));  u64 a11B = pk(fabsf(g1b[4]), fabsf(g2b[4]));
    u64 a20A = pk(fabsf(g1a[6]), fabsf(g2a[6]));  u64 a20B = pk(fabsf(g1b[6]), fabsf(g2b[6]));
    u64 a21A = pk(fabsf(g1a[7]), fabsf(g2a[7]));  u64 a21B = pk(fabsf(g1b[7]), fabsf(g2b[7]));
    u64 a22A = pk(fabsf(g1a[8]), fabsf(g2a[8]));  u64 a22B = pk(fabsf(g1b[8]), fabsf(g2b[8]));

    const u64 THIRD = bc2(1.0f / 3.0f);
    u64 qA = mul2(add2(add2(a00A, a11A), a22A), THIRD);  u64 qB = mul2(add2(add2(a00B, a11B), a22B), THIRD);
    u64 b00A = sub2(a00A, qA, NEG1);  u64 b00B = sub2(a00B, qB, NEG1);
    u64 b11A = sub2(a11A, qA, NEG1);  u64 b11B = sub2(a11B, qB, NEG1);
    u64 b22A = sub2(a22A, qA, NEG1);  u64 b22B = sub2(a22B, qB, NEG1);
    u64 sq10A = mul2(a10A, a10A);  u64 sq10B = mul2(a10B, a10B);
    u64 sq20A = mul2(a20A, a20A);  u64 sq20B = mul2(a20B, a20B);
    u64 sq21A = mul2(a21A, a21A);  u64 sq21B = mul2(a21B, a21B);
    u64 p1A = add2(add2(sq10A, sq20A), sq21A);  u64 p1B = add2(add2(sq10B, sq20B), sq21B);
    u64 p2A = fma2(b00A, b00A, add2(p1A, p1A));  u64 p2B = fma2(b00B, b00B, add2(p1B, p1B));
    p2A = fma2(b11A, b11A, p2A);  p2B = fma2(b11B, b11B, p2B);
    p2A = fma2(b22A, b22A, p2A);  p2B = fma2(b22B, b22B, p2B);
    const u64 SIXTH = bc2(1.0f / 6.0f);
    u64 xA = mul2(p2A, SIXTH);  u64 xB = mul2(p2B, SIXTH);

    float xAl, xAh, xBl, xBh;
    upk(xA, xAl, xAh);  upk(xB, xBl, xBh);
    float rsAl = f_rsqrt(fmaxf(xAl, 1e-30f));  float rsBl = f_rsqrt(fmaxf(xBl, 1e-30f));
    float rsAh = f_rsqrt(fmaxf(xAh, 1e-30f));  float rsBh = f_rsqrt(fmaxf(xBh, 1e-30f));
    u64 rsA = pk(rsAl, rsAh);  u64 rsB = pk(rsBl, rsBh);
    u64 pA = mul2(xA, rsA);  u64 pB = mul2(xB, rsB);

    u64 t1A = sub2(mul2(b11A, b22A), sq21A, NEG1);  u64 t1B = sub2(mul2(b11B, b22B), sq21B, NEG1);
    u64 t2A = sub2(mul2(a10A, b22A), mul2(a21A, a20A), NEG1);  u64 t2B = sub2(mul2(a10B, b22B), mul2(a21B, a20B), NEG1);
    u64 t3A = sub2(mul2(a10A, a21A), mul2(b11A, a20A), NEG1);  u64 t3B = sub2(mul2(a10B, a21B), mul2(b11B, a20B), NEG1);
    u64 dA = mul2(b00A, t1A);  u64 dB = mul2(b00B, t1B);
    dA = sub2(dA, mul2(a10A, t2A), NEG1);  dB = sub2(dB, mul2(a10B, t2B), NEG1);
    dA = fma2(a20A, t3A, dA);  dB = fma2(a20B, t3B, dB);

    const u64 HALF = bc2(0.5f);
    u64 rA = mul2(mul2(dA, HALF), mul2(mul2(rsA, rsA), rsA));
    u64 rB = mul2(mul2(dB, HALF), mul2(mul2(rsB, rsB), rsB));
    float rAl, rAh, rBl, rBh;
    upk(rA, rAl, rAh);  upk(rB, rBl, rBh);
    rAl = fmaxf(-1.0f, fminf(1.0f, rAl));  rBl = fmaxf(-1.0f, fminf(1.0f, rBl));
    rAh = fmaxf(-1.0f, fminf(1.0f, rAh));  rBh = fmaxf(-1.0f, fminf(1.0f, rBh));

    // ---- acos poly (A&S 4.4.46), packed per stream ----
    u64 avA = pk(fabsf(rAl), fabsf(rAh));  u64 avB = pk(fabsf(rBl), fabsf(rBh));
    u64 ppA = bc2(-0.0012624911f);         u64 ppB = ppA;
    u64 c6 = bc2( 0.0066700901f); ppA = fma2(ppA, avA, c6); ppB = fma2(ppB, avB, c6);
    u64 c5 = bc2(-0.0170881256f); ppA = fma2(ppA, avA, c5); ppB = fma2(ppB, avB, c5);
    u64 c4 = bc2( 0.0308918810f); ppA = fma2(ppA, avA, c4); ppB = fma2(ppB, avB, c4);
    u64 c3 = bc2(-0.0501743046f); ppA = fma2(ppA, avA, c3); ppB = fma2(ppB, avB, c3);
    u64 c2 = bc2( 0.0889789874f); ppA = fma2(ppA, avA, c2); ppB = fma2(ppB, avB, c2);
    u64 c1 = bc2(-0.2145988016f); ppA = fma2(ppA, avA, c1); ppB = fma2(ppB, avB, c1);
    u64 c0 = bc2( 1.5707963050f); ppA = fma2(ppA, avA, c0); ppB = fma2(ppB, avB, c0);
    float pAl, pAh, pBl, pBh;
    upk(ppA, pAl, pAh);  upk(ppB, pBl, pBh);

    float qAl, qAh, qBl, qBh;  upk(qA, qAl, qAh);  upk(qB, qBl, qBh);
    float spAl, spAh, spBl, spBh;  upk(pA, spAl, spAh);  upk(pB, spBl, spBh);

    float tAl = f_sqrt(fmaxf(1.0f - fabsf(rAl), 0.0f)) * pAl;
    float tBl = f_sqrt(fmaxf(1.0f - fabsf(rBl), 0.0f)) * pBl;
    float tAh = f_sqrt(fmaxf(1.0f - fabsf(rAh), 0.0f)) * pAh;
    float tBh = f_sqrt(fmaxf(1.0f - fabsf(rBh), 0.0f)) * pBh;
    float acAl = (rAl < 0.0f) ? (PI_F - tAl) : tAl;  float acBl = (rBl < 0.0f) ? (PI_F - tBl) : tBl;
    float acAh = (rAh < 0.0f) ? (PI_F - tAh) : tAh;  float acBh = (rBh < 0.0f) ? (PI_F - tBh) : tBh;

    // ---- eigenvalues per half (4 independent halves; MUFU cos batched) ----
    float phiAl = acAl * (1.0f / 3.0f);  float phiBl = acBl * (1.0f / 3.0f);
    float phiAh = acAh * (1.0f / 3.0f);  float phiBh = acBh * (1.0f / 3.0f);
    float c0Al = f_cos(phiAl);  float c0Bl = f_cos(phiBl);
    float c0Ah = f_cos(phiAh);  float c0Bh = f_cos(phiBh);
    float c2Al = f_cos(phiAl + TWOPI3);  float c2Bl = f_cos(phiBl + TWOPI3);
    float c2Ah = f_cos(phiAh + TWOPI3);  float c2Bh = f_cos(phiBh + TWOPI3);
    float tpAl = 2.0f * spAl, tpAh = 2.0f * spAh, tpBl = 2.0f * spBl, tpBh = 2.0f * spBh;
    float w0Al = fmaf(tpAl, c0Al, qAl);  float w0Bl = fmaf(tpBl, c0Bl, qBl);
    float w2Al = fmaf(tpAl, c2Al, qAl);  float w2Bl = fmaf(tpBl, c2Bl, qBl);
    float w1Al = 3.0f * qAl - w0Al - w2Al;  float w1Bl = 3.0f * qBl - w0Bl - w2Bl;
    float w0Ah = fmaf(tpAh, c0Ah, qAh);  float w0Bh = fmaf(tpBh, c0Bh, qBh);
    float w2Ah = fmaf(tpAh, c2Ah, qAh);  float w2Bh = fmaf(tpBh, c2Bh, qBh);
    float w1Ah = 3.0f * qAh - w0Ah - w2Ah;  float w1Bh = 3.0f * qBh - w0Bh - w2Bh;

    // ---- 4 independent divided-difference tails ----
    float aAl, bAl, gAl, aAh, bAh, gAh, aBl, bBl, gBl, aBh, bBh, gBh;
    divdiff(w0Al, w1Al, w2Al, aAl, bAl, gAl);
    divdiff(w0Bl, w1Bl, w2Bl, aBl, bBl, gBl);
    divdiff(w0Ah, w1Ah, w2Ah, aAh, bAh, gAh);
    divdiff(w0Bh, w1Bh, w2Bh, aBh, bBh, gBh);
    u64 alpA = pk(aAl, aAh);  u64 alpB = pk(aBl, aBh);
    u64 betA = pk(bAl, bAh);  u64 betB = pk(bBl, bBh);
    u64 gamA = pk(gAl, gAh);  u64 gamB = pk(gBl, gBh);

    // ---- A^2 entries, packed ----
    u64 s00A = fma2(a00A, a00A, add2(sq10A, sq20A));  u64 s00B = fma2(a00B, a00B, add2(sq10B, sq20B));
    u64 s11A = fma2(a11A, a11A, add2(sq10A, sq21A));  u64 s11B = fma2(a11B, a11B, add2(sq10B, sq21B));
    u64 s22A = fma2(a22A, a22A, add2(sq20A, sq21A));  u64 s22B = fma2(a22B, a22B, add2(sq20B, sq21B));
    u64 s10A = fma2(a10A, add2(a00A, a11A), mul2(a20A, a21A));  u64 s10B = fma2(a10B, add2(a00B, a11B), mul2(a20B, a21B));
    u64 s20A = fma2(a20A, add2(a00A, a22A), mul2(a10A, a21A));  u64 s20B = fma2(a20B, add2(a00B, a22B), mul2(a10B, a21B));
    u64 s21A = fma2(a21A, add2(a11A, a22A), mul2(a10A, a20A));  u64 s21B = fma2(a21B, add2(a11B, a22B), mul2(a10B, a20B));

    // ---- L = alp*I + bet*A + gam*A^2 ----
    u64 L00A = fma2(gamA, s00A, fma2(betA, a00A, alpA));  u64 L00B = fma2(gamB, s00B, fma2(betB, a00B, alpB));
    u64 L11A = fma2(gamA, s11A, fma2(betA, a11A, alpA));  u64 L11B = fma2(gamB, s11B, fma2(betB, a11B, alpB));
    u64 L22A = fma2(gamA, s22A, fma2(betA, a22A, alpA));  u64 L22B = fma2(gamB, s22B, fma2(betB, a22B, alpB));
    u64 L10A = fma2(gamA, s10A, mul2(betA, a10A));  u64 L10B = fma2(gamB, s10B, mul2(betB, a10B));
    u64 L20A = fma2(gamA, s20A, mul2(betA, a20A));  u64 L20B = fma2(gamB, s20B, mul2(betB, a20B));
    u64 L21A = fma2(gamA, s21A, mul2(betA, a21A));  u64 L21B = fma2(gamB, s21B, mul2(betB, a21B));

    // ---- cross-half differences, squared ----
    float sA = 0.0f, sB = 0.0f, u, v, t;
    upk(L00A, u, v); t = u - v; sA = fmaf(t, t, sA);
    upk(L00B, u, v); t = u - v; sB = fmaf(t, t, sB);
    upk(L11A, u, v); t = u - v; sA = fmaf(t, t, sA);
    upk(L11B, u, v); t = u - v; sB = fmaf(t, t, sB);
    upk(L22A, u, v); t = u - v; sA = fmaf(t, t, sA);
    upk(L22B, u, v); t = u - v; sB = fmaf(t, t, sB);
    upk(L10A, u, v); t = u - v; sA = fmaf(2.0f * t, t, sA);
    upk(L10B, u, v); t = u - v; sB = fmaf(2.0f * t, t, sB);
    upk(L20A, u, v); t = u - v; sA = fmaf(2.0f * t, t, sA);
    upk(L20B, u, v); t = u - v; sB = fmaf(2.0f * t, t, sB);
    upk(L21A, u, v); t = u - v; sA = fmaf(2.0f * t, t, sA);
    upk(L21B, u, v); t = u - v; sB = fmaf(2.0f * t, t, sB);
    outA = sA;
    outB = sB;
}

__global__ void __launch_bounds__(256)
loss_kernel(const float* __restrict__ d1, const float* __restrict__ d2,
            int nmat, float* __restrict__ out, double inv_n, unsigned int nblocks) {
    int base = (blockIdx.x * blockDim.x + threadIdx.x) * 2;
    float s = 0.0f;
    if (base < nmat) {
        // tail handling: clamp B's index and weight its contribution 0/1
        int ib = min(base + 1, nmat - 1);
        float wB = (base + 1 < nmat) ? 1.0f : 0.0f;
        size_t offA = (size_t)base * 9;
        size_t offB = (size_t)ib * 9;
        float oA, oB;
        pair2(d1 + offA, d2 + offA, d1 + offB, d2 + offB, oA, oB);
        s = fmaf(wB, oB, oA);
    }

    // ---- block reduction ----
    #pragma unroll
    for (int off = 16; off > 0; off >>= 1)
        s += __shfl_xor_sync(0xffffffffu, s, off);

    __shared__ float sh[8];
    int lane = threadIdx.x & 31;
    int warp = threadIdx.x >> 5;
    if (lane == 0) sh[warp] = s;
    __syncthreads();
    if (warp == 0) {
        float v = (lane < 8) ? sh[lane] : 0.0f;
        #pragma unroll
        for (int off = 4; off > 0; off >>= 1)
            v += __shfl_xor_sync(0xffu, v, off);
        if (lane == 0) {
            atomicAdd(&g_accum, (double)v);
            __threadfence();
            unsigned int ticket = atomicInc(&g_count, nblocks - 1u);
            if (ticket == nblocks - 1u) {
                out[0] = (float)(g_accum * inv_n);
                g_accum = 0.0;    // restore invariant for next call/replay
            }
        }
    }
}

extern "C" void kernel_launch(void* const* d_in, const int* in_sizes, int n_in,
                              void* d_out, int out_size) {
    const float* d1 = (const float*)d_in[0];
    const float* d2 = (const float*)d_in[1];
    int n_elems = in_sizes[0];          // nmat * 9
    int nmat = n_elems / 9;

    int threads = 256;
    int per_block = threads * 2;
    unsigned int blocks = (unsigned int)((nmat + per_block - 1) / per_block);
    double inv_n = LN2SQ / (double)n_elems;
    loss_kernel<<<blocks, threads>>>(d1, d2, nmat, (float*)d_out, inv_n, blocks);
}

// round 9
// speedup vs baseline: 1.3961x; 1.3961x over previous
#include <cuda_runtime.h>
#include <math.h>
#include <stdint.h>

// ln(2)^2 — final scale converting lg2-unit squared-loss into natural-log units
#define LN2SQ 0.4804530139182014

// statically-zeroed accumulators; kernel self-resets them after each use,
// so the zero-invariant holds across the correctness run and every graph replay.
__device__ double g_accum = 0.0;
__device__ unsigned int g_count = 0u;

// ---- flag-independent fast approx intrinsics (MUFU paths) ----
__device__ __forceinline__ float f_rcp(float x)   { float y; asm("rcp.approx.f32 %0, %1;"   : "=f"(y) : "f"(x)); return y; }
__device__ __forceinline__ float f_rsqrt(float x) { float y; asm("rsqrt.approx.f32 %0, %1;" : "=f"(y) : "f"(x)); return y; }
__device__ __forceinline__ float f_sqrt(float x)  { float y; asm("sqrt.approx.f32 %0, %1;"  : "=f"(y) : "f"(x)); return y; }
__device__ __forceinline__ float f_lg2(float x)   { float y; asm("lg2.approx.f32 %0, %1;"   : "=f"(y) : "f"(x)); return y; }
__device__ __forceinline__ float f_cos(float x)   { float y; asm("cos.approx.f32 %0, %1;"   : "=f"(y) : "f"(x)); return y; }

// Abramowitz & Stegun 4.4.46: |err| <= 2e-8 rad on [0,1], extended to [-1,1]
__device__ __forceinline__ float fast_acos(float r) {
    float a = fabsf(r);
    float p = -0.0012624911f;
    p = fmaf(p, a,  0.0066700901f);
    p = fmaf(p, a, -0.0170881256f);
    p = fmaf(p, a,  0.0308918810f);
    p = fmaf(p, a, -0.0501743046f);
    p = fmaf(p, a,  0.0889789874f);
    p = fmaf(p, a, -0.2145988016f);
    p = fmaf(p, a,  1.5707963050f);
    float t = f_sqrt(fmaxf(1.0f - a, 0.0f)) * p;
    return (r < 0.0f) ? (3.14159265359f - t) : t;
}

struct Sym3 { float m00, m10, m11, m20, m21, m22; };

// logm (in lg2 units) of a 3x3 SPD matrix.
//  - no +EPS*I post-shift (cancels in the difference)
//  - no isfinite sanitize (inputs are B@B^T + 0.05I: finite)
//  - divided differences: gaps are CLAMPED to 2e-4*q (far above the ~1e-6*q
//    eigenvalue noise of the approx-trig path, so no negative/zero gaps — the
//    R4 failure), and a SINGLE rcp of the gap product replaces three rcps:
//      1/e01 = e12*e02*rall,  gam = (df01*e12 - df12*e01)*rall.
//    Clamped-gap error is self-damped by the Newton form: <= ~3e-4 absolute,
//    only on near-degenerate spectra (rare) — negligible in the MSE.
__device__ __forceinline__ void log_spd3(const float* __restrict__ g, Sym3& L) {
    float a00 = fabsf(g[0]);
    float a10 = fabsf(g[3]);
    float a11 = fabsf(g[4]);
    float a20 = fabsf(g[6]);
    float a21 = fabsf(g[7]);
    float a22 = fabsf(g[8]);

    // ---- eigenvalues: trigonometric method (Smith) ----
    float q   = (a00 + a11 + a22) * (1.0f / 3.0f);
    float b00 = a00 - q, b11 = a11 - q, b22 = a22 - q;
    float p1  = a10 * a10 + a20 * a20 + a21 * a21;
    float p2  = b00 * b00 + b11 * b11 + b22 * b22 + 2.0f * p1;
    float x   = p2 * (1.0f / 6.0f);
    float rs  = f_rsqrt(fmaxf(x, 1e-30f));   // 1/sqrt(x)
    float p   = x * rs;                      // sqrt(x)

    float detB = b00 * (b11 * b22 - a21 * a21)
               - a10 * (a10 * b22 - a21 * a20)
               + a20 * (a10 * a21 - b11 * a20);
    float r = 0.5f * detB * rs * rs * rs;
    r = fmaxf(-1.0f, fminf(1.0f, r));        // also squashes NaN -> 1

    float phi = fast_acos(r) * (1.0f / 3.0f);
    float w0 = q + 2.0f * p * f_cos(phi);                          // largest
    float w2 = q + 2.0f * p * f_cos(phi + 2.0943951023931953f);    // smallest
    float w1 = 3.0f * q - w0 - w2;                                 // middle

    // logs in base-2; final loss rescaled once by ln(2)^2
    float f0 = f_lg2(w0);
    float f1 = f_lg2(w1);
    float f2 = f_lg2(w2);

    // ---- branch-free Newton divided differences, ONE rcp ----
    float dlt = 2e-4f * q;
    float e01 = fmaxf(w0 - w1, dlt);
    float e12 = fmaxf(w1 - w2, dlt);
    float e02 = e01 + e12;
    float rall = f_rcp(e01 * (e12 * e02));
    float df01 = f0 - f1;
    float df12 = f1 - f2;
    float d01 = df01 * (e12 * e02) * rall;
    float gam = fmaf(df01, e12, -df12 * e01) * rall;
    float bet = d01 - gam * (w0 + w1);
    float alp = f0 - d01 * w0 + gam * (w0 * w1);

    // ---- A^2 (symmetric, 6 unique entries) ----
    float s00 = a00 * a00 + a10 * a10 + a20 * a20;
    float s11 = a10 * a10 + a11 * a11 + a21 * a21;
    float s22 = a20 * a20 + a21 * a21 + a22 * a22;
    float s10 = a10 * (a00 + a11) + a20 * a21;
    float s20 = a20 * (a00 + a22) + a10 * a21;
    float s21 = a21 * (a11 + a22) + a10 * a20;

    L.m00 = alp + bet * a00 + gam * s00;
    L.m11 = alp + bet * a11 + gam * s11;
    L.m22 = alp + bet * a22 + gam * s22;
    L.m10 = bet * a10 + gam * s10;
    L.m20 = bet * a20 + gam * s20;
    L.m21 = bet * a21 + gam * s21;
}

__global__ void __launch_bounds__(256)
loss_kernel(const float* __restrict__ d1, const float* __restrict__ d2,
            int nmat, float* __restrict__ out, double inv_n, unsigned int nblocks) {
    int i = blockIdx.x * blockDim.x + threadIdx.x;
    float s = 0.0f;
    if (i < nmat) {
        size_t off = (size_t)i * 9;
        Sym3 L1, L2;
        log_spd3(d1 + off, L1);
        log_spd3(d2 + off, L2);
        float t;
        t = L1.m00 - L2.m00; s = fmaf(t, t, s);
        t = L1.m11 - L2.m11; s = fmaf(t, t, s);
        t = L1.m22 - L2.m22; s = fmaf(t, t, s);
        t = L1.m10 - L2.m10; s = fmaf(2.0f * t, t, s);   // off-diagonals count twice
        t = L1.m20 - L2.m20; s = fmaf(2.0f * t, t, s);
        t = L1.m21 - L2.m21; s = fmaf(2.0f * t, t, s);
    }

    // ---- block reduction ----
    #pragma unroll
    for (int off = 16; off > 0; off >>= 1)
        s += __shfl_xor_sync(0xffffffffu, s, off);

    __shared__ float sh[8];
    int lane = threadIdx.x & 31;
    int warp = threadIdx.x >> 5;
    if (lane == 0) sh[warp] = s;
    __syncthreads();
    if (warp == 0) {
        float v = (lane < 8) ? sh[lane] : 0.0f;
        #pragma unroll
        for (int off = 4; off > 0; off >>= 1)
            v += __shfl_xor_sync(0xffu, v, off);
        if (lane == 0) {
            atomicAdd(&g_accum, (double)v);
            __threadfence();
            // ticket wraps to 0 at nblocks-1: self-resets for the next replay
            unsigned int ticket = atomicInc(&g_count, nblocks - 1u);
            if (ticket == nblocks - 1u) {
                out[0] = (float)(g_accum * inv_n);
                g_accum = 0.0;    // restore invariant for next call/replay
            }
        }
    }
}

extern "C" void kernel_launch(void* const* d_in, const int* in_sizes, int n_in,
                              void* d_out, int out_size) {
    const float* d1 = (const float*)d_in[0];
    const float* d2 = (const float*)d_in[1];
    int n_elems = in_sizes[0];          // nmat * 9
    int nmat = n_elems / 9;

    int threads = 256;
    unsigned int blocks = (unsigned int)((nmat + threads - 1) / threads);
    // inv_n includes the ln(2)^2 rescale (logs computed in base 2)
    double inv_n = LN2SQ / (double)n_elems;
    loss_kernel<<<blocks, threads>>>(d1, d2, nmat, (float*)d_out, inv_n, blocks);
}